// round 12
// baseline (speedup 1.0000x reference)
#include <cuda_runtime.h>
#include <math.h>

// Persistent scratch (zero-init at load; last block resets each call so graph
// replays are deterministic).
__device__ float        g_total;  // sum of ||err|| over ALL points, all batches
__device__ unsigned int g_count;  // block arrival counter

__device__ __forceinline__ float fsqrt_approx(float v) {
    float r;
    asm("sqrt.approx.f32 %0, %1;" : "=f"(r) : "f"(v));
    return r;
}

__device__ __forceinline__ void quat_to_rot(float qw, float qx, float qy, float qz, float* R) {
    float inv = rsqrtf(qw * qw + qx * qx + qy * qy + qz * qz);
    qw *= inv; qx *= inv; qy *= inv; qz *= inv;
    R[0] = 1.f - 2.f * (qy * qy + qz * qz);
    R[1] = 2.f * (qx * qy - qz * qw);
    R[2] = 2.f * (qx * qz + qy * qw);
    R[3] = 2.f * (qx * qy + qz * qw);
    R[4] = 1.f - 2.f * (qx * qx + qz * qz);
    R[5] = 2.f * (qy * qz - qx * qw);
    R[6] = 2.f * (qx * qz - qy * qw);
    R[7] = 2.f * (qy * qz + qx * qw);
    R[8] = 1.f - 2.f * (qx * qx + qy * qy);
}

struct Xf {
    float a00, a01, a02, a10, a11, a12, a20, a21, a22, t0, t1, t2;
};

// Direct residual form: numerically safe (residuals are small & exact-ish).
__device__ __forceinline__ float pnorm(const Xf& m, float x, float y, float z) {
    float dx = fmaf(m.a00, x, fmaf(m.a01, y, fmaf(m.a02, z, m.t0)));
    float dy = fmaf(m.a10, x, fmaf(m.a11, y, fmaf(m.a12, z, m.t1)));
    float dz = fmaf(m.a20, x, fmaf(m.a21, y, fmaf(m.a22, z, m.t2)));
    return fsqrt_approx(fmaf(dx, dx, fmaf(dy, dy, dz * dz)));
}

__device__ __forceinline__ float do4(const Xf& m, float4 vx, float4 vy, float4 vz) {
    float r0 = pnorm(m, vx.x, vy.x, vz.x) + pnorm(m, vx.y, vy.y, vz.y);
    float r1 = pnorm(m, vx.z, vy.z, vz.z) + pnorm(m, vx.w, vy.w, vz.w);
    return r0 + r1;
}

__global__ void __launch_bounds__(256) fused_kernel(
    const float* __restrict__ pc,
    const float* __restrict__ tgt_t,
    const float* __restrict__ tgt_r,
    const float* __restrict__ err_t,
    const float* __restrict__ err_r,
    float* __restrict__ out,
    int B, int N, unsigned int totalBlocks)
{
    int b = blockIdx.y;

    // ---- per-batch rigid transform (redundant per thread; hidden under mem) ----
    float Rt[9], Rp[9];
    quat_to_rot(tgt_r[4*b+0], tgt_r[4*b+1], tgt_r[4*b+2], tgt_r[4*b+3], Rt);
    quat_to_rot(err_r[4*b+0], err_r[4*b+1], err_r[4*b+2], err_r[4*b+3], Rp);

    Xf m;
    m.a00 = Rp[0]*Rt[0] + Rp[3]*Rt[3] + Rp[6]*Rt[6] - 1.f;
    m.a01 = Rp[0]*Rt[1] + Rp[3]*Rt[4] + Rp[6]*Rt[7];
    m.a02 = Rp[0]*Rt[2] + Rp[3]*Rt[5] + Rp[6]*Rt[8];
    m.a10 = Rp[1]*Rt[0] + Rp[4]*Rt[3] + Rp[7]*Rt[6];
    m.a11 = Rp[1]*Rt[1] + Rp[4]*Rt[4] + Rp[7]*Rt[7] - 1.f;
    m.a12 = Rp[1]*Rt[2] + Rp[4]*Rt[5] + Rp[7]*Rt[8];
    m.a20 = Rp[2]*Rt[0] + Rp[5]*Rt[3] + Rp[8]*Rt[6];
    m.a21 = Rp[2]*Rt[1] + Rp[5]*Rt[4] + Rp[8]*Rt[7];
    m.a22 = Rp[2]*Rt[2] + Rp[5]*Rt[5] + Rp[8]*Rt[8] - 1.f;

    float d0 = tgt_t[3*b+0] - err_t[3*b+0];
    float d1 = tgt_t[3*b+1] - err_t[3*b+1];
    float d2 = tgt_t[3*b+2] - err_t[3*b+2];
    m.t0 = Rp[0]*d0 + Rp[3]*d1 + Rp[6]*d2;
    m.t1 = Rp[1]*d0 + Rp[4]*d1 + Rp[7]*d2;
    m.t2 = Rp[2]*d0 + Rp[5]*d1 + Rp[8]*d2;

    // ---- stream points: branch-free pair loop, MLP = 6 loads in flight ----
    const float* base = pc + (size_t)b * 4 * (size_t)N;
    float accA = 0.f, accB = 0.f;

    if ((N & 3) == 0) {
        int nvec   = N >> 2;
        int stride = gridDim.x * blockDim.x;
        const float4* X = (const float4*)(base);
        const float4* Y = (const float4*)(base + N);
        const float4* Z = (const float4*)(base + 2 * (size_t)N);

        int i = blockIdx.x * blockDim.x + threadIdx.x;
        for (; i + stride < nvec; i += 2 * stride) {
            int j = i + stride;
            float4 x0 = __ldcs(X + i);
            float4 y0 = __ldcs(Y + i);
            float4 z0 = __ldcs(Z + i);
            float4 x1 = __ldcs(X + j);
            float4 y1 = __ldcs(Y + j);
            float4 z1 = __ldcs(Z + j);
            accA += do4(m, x0, y0, z0);
            accB += do4(m, x1, y1, z1);
        }
        if (i < nvec) {
            float4 x0 = __ldcs(X + i);
            float4 y0 = __ldcs(Y + i);
            float4 z0 = __ldcs(Z + i);
            accA += do4(m, x0, y0, z0);
        }
    } else {
        for (int n = blockIdx.x * blockDim.x + threadIdx.x; n < N;
             n += gridDim.x * blockDim.x) {
            accA += pnorm(m, base[n], base[N + n], base[2*(size_t)N + n]);
        }
    }

    float acc = accA + accB;

    // ---- block reduction ----
    __shared__ float s[256];
    __shared__ int   s_last;
    s[threadIdx.x] = acc;
    __syncthreads();
    for (int st = blockDim.x >> 1; st >= 32; st >>= 1) {
        if (threadIdx.x < st) s[threadIdx.x] += s[threadIdx.x + st];
        __syncthreads();
    }
    if (threadIdx.x < 32) {
        float v = s[threadIdx.x];
        #pragma unroll
        for (int off = 16; off > 0; off >>= 1)
            v += __shfl_down_sync(0xFFFFFFFFu, v, off);
        if (threadIdx.x == 0) {
            atomicAdd(&g_total, v);
            __threadfence();
            unsigned prev = atomicAdd(&g_count, 1u);
            s_last = (prev == totalBlocks - 1u) ? 1 : 0;
        }
    }
    __syncthreads();

    // ---- last block: pose loss + combine + reset ----
    if (s_last) {
        float lt = 0.f, lr = 0.f;
        for (int bb = threadIdx.x; bb < B; bb += blockDim.x) {
            #pragma unroll
            for (int k = 0; k < 3; k++) {
                float d = fabsf(err_t[3*bb+k] - tgt_t[3*bb+k]);
                lt += (d < 1.f) ? 0.5f*d*d : d - 0.5f;
            }
            float q0 = err_r[4*bb+0], q1 = err_r[4*bb+1], q2 = err_r[4*bb+2], q3 = err_r[4*bb+3];
            float r0 = tgt_r[4*bb+0], r1 = -tgt_r[4*bb+1], r2 = -tgt_r[4*bb+2], r3 = -tgt_r[4*bb+3];
            float w = q0*r0 - q1*r1 - q2*r2 - q3*r3;
            float x = q0*r1 + q1*r0 + q2*r3 - q3*r2;
            float y = q0*r2 - q1*r3 + q2*r0 + q3*r1;
            float z = q0*r3 + q1*r2 - q2*r1 + q3*r0;
            float angle = 2.f * atan2f(sqrtf(x*x + y*y + z*z), fabsf(w));
            lr += angle * (180.f / 3.14159265358979323846f);
        }
        __shared__ float s2[256];
        s[threadIdx.x]  = lt;
        s2[threadIdx.x] = lr;
        __syncthreads();
        for (int st = blockDim.x >> 1; st > 0; st >>= 1) {
            if (threadIdx.x < st) {
                s[threadIdx.x]  += s[threadIdx.x + st];
                s2[threadIdx.x] += s2[threadIdx.x + st];
            }
            __syncthreads();
        }
        if (threadIdx.x == 0) {
            float loss_transl = s[0] / (float)B;
            float loss_rot    = s2[0] / (float)B;
            float pose_loss   = loss_transl + loss_rot;       // RESCALE_* = 1
            float total = *((volatile float*)&g_total);
            float pcl_over_B = (total / (float)N) / (float)B;
            out[0] = 0.5f * pose_loss + 0.5f * pcl_over_B;    // WEIGHT_PC = 0.5
            out[1] = loss_transl;
            out[2] = loss_rot;
            out[3] = pcl_over_B;
            g_total = 0.f;
            g_count = 0u;
            __threadfence();
        }
    }
}

extern "C" void kernel_launch(void* const* d_in, const int* in_sizes, int n_in,
                              void* d_out, int out_size) {
    const float* pc = (const float*)d_in[0];   // [B,4,N]
    const float* tt = (const float*)d_in[1];   // [B,3]
    const float* tr = (const float*)d_in[2];   // [B,4]
    const float* te = (const float*)d_in[3];   // [B,3]
    const float* re = (const float*)d_in[4];   // [B,4]

    int B = in_sizes[1] / 3;
    int N = in_sizes[0] / (4 * B);

    // Single-wave sizing: ~740 concurrent blocks on 148 SMs at 5 blocks/SM.
    int blocksPerBatch = 736 / (B > 0 ? B : 1);
    if (blocksPerBatch < 1) blocksPerBatch = 1;
    if (blocksPerBatch > 128) blocksPerBatch = 128;
    // don't launch more blocks than work
    if ((N & 3) == 0) {
        int nvec = N >> 2;
        int maxB = (nvec + 255) / 256;
        if (blocksPerBatch > maxB) blocksPerBatch = maxB;
    }

    dim3 grid(blocksPerBatch, B);
    unsigned totalBlocks = (unsigned)blocksPerBatch * (unsigned)B;

    fused_kernel<<<grid, 256>>>(pc, tt, tr, te, re, (float*)d_out,
                                B, N, totalBlocks);
}

// round 13
// speedup vs baseline: 1.4320x; 1.4320x over previous
#include <cuda_runtime.h>
#include <math.h>

// Persistent scratch (zero-init at load; last block resets each call so graph
// replays are deterministic).
__device__ float        g_total;  // sum of ||err|| over ALL points, all batches
__device__ unsigned int g_count;  // block arrival counter

__device__ __forceinline__ float fsqrt_approx(float v) {
    float r;
    asm("sqrt.approx.f32 %0, %1;" : "=f"(r) : "f"(v));
    return r;
}

__device__ __forceinline__ void quat_to_rot(float qw, float qx, float qy, float qz, float* R) {
    float inv = rsqrtf(qw * qw + qx * qx + qy * qy + qz * qz);
    qw *= inv; qx *= inv; qy *= inv; qz *= inv;
    R[0] = 1.f - 2.f * (qy * qy + qz * qz);
    R[1] = 2.f * (qx * qy - qz * qw);
    R[2] = 2.f * (qx * qz + qy * qw);
    R[3] = 2.f * (qx * qy + qz * qw);
    R[4] = 1.f - 2.f * (qx * qx + qz * qz);
    R[5] = 2.f * (qy * qz - qx * qw);
    R[6] = 2.f * (qx * qz - qy * qw);
    R[7] = 2.f * (qy * qz + qx * qw);
    R[8] = 1.f - 2.f * (qx * qx + qy * qy);
}

struct Xf {
    float a00, a01, a02, a10, a11, a12, a20, a21, a22, t0, t1, t2;
};

// Direct residual form: numerically safe (residuals are small & exact-ish).
__device__ __forceinline__ float pnorm(const Xf& m, float x, float y, float z) {
    float dx = fmaf(m.a00, x, fmaf(m.a01, y, fmaf(m.a02, z, m.t0)));
    float dy = fmaf(m.a10, x, fmaf(m.a11, y, fmaf(m.a12, z, m.t1)));
    float dz = fmaf(m.a20, x, fmaf(m.a21, y, fmaf(m.a22, z, m.t2)));
    return fsqrt_approx(fmaf(dx, dx, fmaf(dy, dy, dz * dz)));
}

__device__ __forceinline__ float do4(const Xf& m, float4 vx, float4 vy, float4 vz) {
    float r0 = pnorm(m, vx.x, vy.x, vz.x) + pnorm(m, vx.y, vy.y, vz.y);
    float r1 = pnorm(m, vx.z, vy.z, vz.z) + pnorm(m, vx.w, vy.w, vz.w);
    return r0 + r1;
}

__global__ void __launch_bounds__(256) fused_kernel(
    const float* __restrict__ pc,
    const float* __restrict__ tgt_t,
    const float* __restrict__ tgt_r,
    const float* __restrict__ err_t,
    const float* __restrict__ err_r,
    float* __restrict__ out,
    int B, int N, unsigned int totalBlocks)
{
    int b = blockIdx.y;

    // ---- per-batch rigid transform (redundant per thread; hidden under mem) ----
    float Rt[9], Rp[9];
    quat_to_rot(tgt_r[4*b+0], tgt_r[4*b+1], tgt_r[4*b+2], tgt_r[4*b+3], Rt);
    quat_to_rot(err_r[4*b+0], err_r[4*b+1], err_r[4*b+2], err_r[4*b+3], Rp);

    Xf m;
    m.a00 = Rp[0]*Rt[0] + Rp[3]*Rt[3] + Rp[6]*Rt[6] - 1.f;
    m.a01 = Rp[0]*Rt[1] + Rp[3]*Rt[4] + Rp[6]*Rt[7];
    m.a02 = Rp[0]*Rt[2] + Rp[3]*Rt[5] + Rp[6]*Rt[8];
    m.a10 = Rp[1]*Rt[0] + Rp[4]*Rt[3] + Rp[7]*Rt[6];
    m.a11 = Rp[1]*Rt[1] + Rp[4]*Rt[4] + Rp[7]*Rt[7] - 1.f;
    m.a12 = Rp[1]*Rt[2] + Rp[4]*Rt[5] + Rp[7]*Rt[8];
    m.a20 = Rp[2]*Rt[0] + Rp[5]*Rt[3] + Rp[8]*Rt[6];
    m.a21 = Rp[2]*Rt[1] + Rp[5]*Rt[4] + Rp[8]*Rt[7];
    m.a22 = Rp[2]*Rt[2] + Rp[5]*Rt[5] + Rp[8]*Rt[8] - 1.f;

    float d0 = tgt_t[3*b+0] - err_t[3*b+0];
    float d1 = tgt_t[3*b+1] - err_t[3*b+1];
    float d2 = tgt_t[3*b+2] - err_t[3*b+2];
    m.t0 = Rp[0]*d0 + Rp[3]*d1 + Rp[6]*d2;
    m.t1 = Rp[1]*d0 + Rp[4]*d1 + Rp[7]*d2;
    m.t2 = Rp[2]*d0 + Rp[5]*d1 + Rp[8]*d2;

    // ---- stream points: branch-free pair loop, MLP = 6 loads in flight ----
    const float* base = pc + (size_t)b * 4 * (size_t)N;
    float accA = 0.f, accB = 0.f;

    if ((N & 3) == 0) {
        int nvec   = N >> 2;
        int stride = gridDim.x * blockDim.x;
        const float4* X = (const float4*)(base);
        const float4* Y = (const float4*)(base + N);
        const float4* Z = (const float4*)(base + 2 * (size_t)N);

        int i = blockIdx.x * blockDim.x + threadIdx.x;
        for (; i + stride < nvec; i += 2 * stride) {
            int j = i + stride;
            float4 x0 = __ldcs(X + i);
            float4 y0 = __ldcs(Y + i);
            float4 z0 = __ldcs(Z + i);
            float4 x1 = __ldcs(X + j);
            float4 y1 = __ldcs(Y + j);
            float4 z1 = __ldcs(Z + j);
            accA += do4(m, x0, y0, z0);
            accB += do4(m, x1, y1, z1);
        }
        if (i < nvec) {
            float4 x0 = __ldcs(X + i);
            float4 y0 = __ldcs(Y + i);
            float4 z0 = __ldcs(Z + i);
            accA += do4(m, x0, y0, z0);
        }
    } else {
        for (int n = blockIdx.x * blockDim.x + threadIdx.x; n < N;
             n += gridDim.x * blockDim.x) {
            accA += pnorm(m, base[n], base[N + n], base[2*(size_t)N + n]);
        }
    }

    float acc = accA + accB;

    // ---- block reduction ----
    __shared__ float s[256];
    __shared__ int   s_last;
    s[threadIdx.x] = acc;
    __syncthreads();
    for (int st = blockDim.x >> 1; st >= 32; st >>= 1) {
        if (threadIdx.x < st) s[threadIdx.x] += s[threadIdx.x + st];
        __syncthreads();
    }
    if (threadIdx.x < 32) {
        float v = s[threadIdx.x];
        #pragma unroll
        for (int off = 16; off > 0; off >>= 1)
            v += __shfl_down_sync(0xFFFFFFFFu, v, off);
        if (threadIdx.x == 0) {
            atomicAdd(&g_total, v);
            __threadfence();
            unsigned prev = atomicAdd(&g_count, 1u);
            s_last = (prev == totalBlocks - 1u) ? 1 : 0;
        }
    }
    __syncthreads();

    // ---- last block: pose loss + combine + reset ----
    if (s_last) {
        float lt = 0.f, lr = 0.f;
        for (int bb = threadIdx.x; bb < B; bb += blockDim.x) {
            #pragma unroll
            for (int k = 0; k < 3; k++) {
                float d = fabsf(err_t[3*bb+k] - tgt_t[3*bb+k]);
                lt += (d < 1.f) ? 0.5f*d*d : d - 0.5f;
            }
            float q0 = err_r[4*bb+0], q1 = err_r[4*bb+1], q2 = err_r[4*bb+2], q3 = err_r[4*bb+3];
            float r0 = tgt_r[4*bb+0], r1 = -tgt_r[4*bb+1], r2 = -tgt_r[4*bb+2], r3 = -tgt_r[4*bb+3];
            float w = q0*r0 - q1*r1 - q2*r2 - q3*r3;
            float x = q0*r1 + q1*r0 + q2*r3 - q3*r2;
            float y = q0*r2 - q1*r3 + q2*r0 + q3*r1;
            float z = q0*r3 + q1*r2 - q2*r1 + q3*r0;
            float angle = 2.f * atan2f(sqrtf(x*x + y*y + z*z), fabsf(w));
            lr += angle * (180.f / 3.14159265358979323846f);
        }
        __shared__ float s2[256];
        s[threadIdx.x]  = lt;
        s2[threadIdx.x] = lr;
        __syncthreads();
        for (int st = blockDim.x >> 1; st > 0; st >>= 1) {
            if (threadIdx.x < st) {
                s[threadIdx.x]  += s[threadIdx.x + st];
                s2[threadIdx.x] += s2[threadIdx.x + st];
            }
            __syncthreads();
        }
        if (threadIdx.x == 0) {
            float loss_transl = s[0] / (float)B;
            float loss_rot    = s2[0] / (float)B;
            float pose_loss   = loss_transl + loss_rot;       // RESCALE_* = 1
            float total = *((volatile float*)&g_total);
            float pcl_over_B = (total / (float)N) / (float)B;
            out[0] = 0.5f * pose_loss + 0.5f * pcl_over_B;    // WEIGHT_PC = 0.5
            out[1] = loss_transl;
            out[2] = loss_rot;
            out[3] = pcl_over_B;
            g_total = 0.f;
            g_count = 0u;
            __threadfence();
        }
    }
}

extern "C" void kernel_launch(void* const* d_in, const int* in_sizes, int n_in,
                              void* d_out, int out_size) {
    const float* pc = (const float*)d_in[0];   // [B,4,N]
    const float* tt = (const float*)d_in[1];   // [B,3]
    const float* tr = (const float*)d_in[2];   // [B,4]
    const float* te = (const float*)d_in[3];   // [B,3]
    const float* re = (const float*)d_in[4];   // [B,4]

    int B = in_sizes[1] / 3;
    int N = in_sizes[0] / (4 * B);

    // Single-wave sizing: ~740 concurrent blocks on 148 SMs at 5 blocks/SM.
    int blocksPerBatch = 736 / (B > 0 ? B : 1);
    if (blocksPerBatch < 1) blocksPerBatch = 1;
    if (blocksPerBatch > 128) blocksPerBatch = 128;
    // don't launch more blocks than work
    if ((N & 3) == 0) {
        int nvec = N >> 2;
        int maxB = (nvec + 255) / 256;
        if (blocksPerBatch > maxB) blocksPerBatch = maxB;
    }

    dim3 grid(blocksPerBatch, B);
    unsigned totalBlocks = (unsigned)blocksPerBatch * (unsigned)B;

    fused_kernel<<<grid, 256>>>(pc, tt, tr, te, re, (float*)d_out,
                                B, N, totalBlocks);
}